// round 9
// baseline (speedup 1.0000x reference)
#include <cuda_runtime.h>
#include <cuda_fp16.h>
#include <cstdint>

#define N_NODES   100000
#define IN_CH     2048
#define OUT_CH    128
#define NNZ_FEAT  2000000
#define NNZ_ADJ   1600000
#define CAP_F     128     // max feat row degree (Poisson(20))
#define CAP_A     96      // max adj  row degree (Poisson(16))

#define NT        256
#define ROWS_PER_BLOCK 16                       // (256/32) warps * 2 rows
#define SPMM_BLOCKS   (N_NODES / ROWS_PER_BLOCK)          // 6250 (exact)
#define SCAT_A_BLOCKS ((NNZ_ADJ  + NT - 1) / NT)          // 6250
#define SCAT_F_BLOCKS ((NNZ_FEAT + NT - 1) / NT)          // 7813
#define ZERO_BLOCKS   ((N_NODES  + NT - 1) / NT)          // 391

// ---------------- static device scratch (no allocations allowed) ----------
// Invariant: g_feat_cnt / g_adj_cnt are ZERO at entry of every call.
// feat cnt is re-zeroed by extra blocks fused into the spmm1 launch (spmm1
// touches only adj data); adj cnt is re-zeroed by the small tail kernel.
__device__ int    g_feat_cnt[N_NODES];
__device__ int    g_adj_cnt [N_NODES];
__device__ int2   g_feat_cv [(size_t)N_NODES * CAP_F];   // .x = col*16, .y = bits(val)
__device__ int2   g_adj_cv  [(size_t)N_NODES * CAP_A];
__device__ __half g_w16     [IN_CH * OUT_CH];
__device__ __half g_ha      [(size_t)N_NODES * OUT_CH];  // ping
__device__ __half g_hb      [(size_t)N_NODES * OUT_CH];  // pong

// ---------------- packed f32x2 FMA (Blackwell FFMA2, PTX-only) -------------
__device__ __forceinline__ unsigned long long pack_dup(float v) {
    unsigned long long r;
    asm("mov.b64 %0, {%1, %1};" : "=l"(r) : "f"(v));
    return r;
}
__device__ __forceinline__ void ffma2(float& x, float& y, float hx, float hy,
                                      unsigned long long vv) {
    asm("{\n\t"
        ".reg .b64 ta, tb;\n\t"
        "mov.b64 ta, {%0, %1};\n\t"
        "mov.b64 tb, {%2, %3};\n\t"
        "fma.rn.f32x2 ta, tb, %4, ta;\n\t"
        "mov.b64 {%0, %1}, ta;\n\t"
        "}"
        : "+f"(x), "+f"(y) : "f"(hx), "f"(hy), "l"(vv));
}

// ---------------- kernel 1: feat scatter + weight convert ------------------
__global__ void scatter_feat_convert_kernel(const int* __restrict__ feat_rows,
                                            const int* __restrict__ feat_cols,
                                            const float* __restrict__ feat_vals,
                                            const float* __restrict__ w) {
    int i = blockIdx.x * blockDim.x + threadIdx.x;
    if (i < NNZ_FEAT) {
        int r = __ldg(feat_rows + i);
        int p = atomicAdd(&g_feat_cnt[r], 1);
        if (p < CAP_F) {
            int2 cv;
            cv.x = __ldg(feat_cols + i) * 16;
            cv.y = __float_as_int(__ldg(feat_vals + i));
            g_feat_cv[(size_t)r * CAP_F + p] = cv;
        }
    }
    if (i < IN_CH * OUT_CH / 4) {
        float4 f = __ldg(reinterpret_cast<const float4*>(w) + i);
        __half2* o = reinterpret_cast<__half2*>(g_w16 + i * 4);
        o[0] = __floats2half2_rn(f.x, f.y);
        o[1] = __floats2half2_rn(f.z, f.w);
    }
}

// ---------------- SPMM core: half-warp per row, 16 lanes x uint4 -----------
// MODE 0: bias+relu, half out.  MODE 1: half out.  MODE 2: float out.
template <int MODE, int CAP>
__device__ __forceinline__ void spmm_body(
        int spmm_block,
        const int* __restrict__ cnt,
        const int2* __restrict__ cv,
        const __half* __restrict__ dense16,
        void* __restrict__ outv,
        const float* __restrict__ bias) {
    int gw   = spmm_block * (NT / 32) + (threadIdx.x >> 5);
    int lane = threadIdx.x & 31;
    int hf   = lane >> 4;
    int hl   = lane & 15;
    int row  = gw * 2 + hf;

    int deg = __ldg(cnt + row);
    if (deg > CAP) deg = CAP;
    int degw = max(deg, __shfl_xor_sync(0xffffffffu, deg, 16));

    const int2* rowcv = cv + (size_t)row * CAP;
    const uint4* dp = reinterpret_cast<const uint4*>(dense16);  // 16 uint4 per row

    float a0=0.f,a1=0.f,a2=0.f,a3=0.f,a4=0.f,a5=0.f,a6=0.f,a7=0.f;

    for (int base = 0; base < degw; base += 16) {
        int n = degw - base;
        if (n > 16) n = 16;
        int2 p = make_int2(0, 0);                 // pad: c16=0, v=0 (harmless)
        if (hl < n && base + hl < deg) p = __ldg(rowcv + base + hl);
        int nq = (n + 3) & ~3;
        for (int k = 0; k < nq; k += 4) {
            int c0 = __shfl_sync(0xffffffffu, p.x, k,     16);
            int c1 = __shfl_sync(0xffffffffu, p.x, k + 1, 16);
            int c2 = __shfl_sync(0xffffffffu, p.x, k + 2, 16);
            int c3 = __shfl_sync(0xffffffffu, p.x, k + 3, 16);
            unsigned long long v0 = pack_dup(__int_as_float(__shfl_sync(0xffffffffu, p.y, k,     16)));
            unsigned long long v1 = pack_dup(__int_as_float(__shfl_sync(0xffffffffu, p.y, k + 1, 16)));
            unsigned long long v2 = pack_dup(__int_as_float(__shfl_sync(0xffffffffu, p.y, k + 2, 16)));
            unsigned long long v3 = pack_dup(__int_as_float(__shfl_sync(0xffffffffu, p.y, k + 3, 16)));
            uint4 h0 = __ldg(dp + c0 + hl);
            uint4 h1 = __ldg(dp + c1 + hl);
            uint4 h2 = __ldg(dp + c2 + hl);
            uint4 h3 = __ldg(dp + c3 + hl);

            float2 f;
            f = __half22float2(*reinterpret_cast<__half2*>(&h0.x)); ffma2(a0,a1,f.x,f.y,v0);
            f = __half22float2(*reinterpret_cast<__half2*>(&h0.y)); ffma2(a2,a3,f.x,f.y,v0);
            f = __half22float2(*reinterpret_cast<__half2*>(&h0.z)); ffma2(a4,a5,f.x,f.y,v0);
            f = __half22float2(*reinterpret_cast<__half2*>(&h0.w)); ffma2(a6,a7,f.x,f.y,v0);

            f = __half22float2(*reinterpret_cast<__half2*>(&h1.x)); ffma2(a0,a1,f.x,f.y,v1);
            f = __half22float2(*reinterpret_cast<__half2*>(&h1.y)); ffma2(a2,a3,f.x,f.y,v1);
            f = __half22float2(*reinterpret_cast<__half2*>(&h1.z)); ffma2(a4,a5,f.x,f.y,v1);
            f = __half22float2(*reinterpret_cast<__half2*>(&h1.w)); ffma2(a6,a7,f.x,f.y,v1);

            f = __half22float2(*reinterpret_cast<__half2*>(&h2.x)); ffma2(a0,a1,f.x,f.y,v2);
            f = __half22float2(*reinterpret_cast<__half2*>(&h2.y)); ffma2(a2,a3,f.x,f.y,v2);
            f = __half22float2(*reinterpret_cast<__half2*>(&h2.z)); ffma2(a4,a5,f.x,f.y,v2);
            f = __half22float2(*reinterpret_cast<__half2*>(&h2.w)); ffma2(a6,a7,f.x,f.y,v2);

            f = __half22float2(*reinterpret_cast<__half2*>(&h3.x)); ffma2(a0,a1,f.x,f.y,v3);
            f = __half22float2(*reinterpret_cast<__half2*>(&h3.y)); ffma2(a2,a3,f.x,f.y,v3);
            f = __half22float2(*reinterpret_cast<__half2*>(&h3.z)); ffma2(a4,a5,f.x,f.y,v3);
            f = __half22float2(*reinterpret_cast<__half2*>(&h3.w)); ffma2(a6,a7,f.x,f.y,v3);
        }
    }

    if (MODE == 0) {
        const float4* b4 = reinterpret_cast<const float4*>(bias);
        float4 b0 = __ldg(b4 + hl * 2);
        float4 b1 = __ldg(b4 + hl * 2 + 1);
        a0 = fmaxf(a0 + b0.x, 0.f); a1 = fmaxf(a1 + b0.y, 0.f);
        a2 = fmaxf(a2 + b0.z, 0.f); a3 = fmaxf(a3 + b0.w, 0.f);
        a4 = fmaxf(a4 + b1.x, 0.f); a5 = fmaxf(a5 + b1.y, 0.f);
        a6 = fmaxf(a6 + b1.z, 0.f); a7 = fmaxf(a7 + b1.w, 0.f);
    }

    if (MODE == 2) {
        float4* o4 = reinterpret_cast<float4*>(outv);
        float4 o;
        o.x = a0; o.y = a1; o.z = a2; o.w = a3;
        o4[(size_t)row * 32 + hl * 2]     = o;
        o.x = a4; o.y = a5; o.z = a6; o.w = a7;
        o4[(size_t)row * 32 + hl * 2 + 1] = o;
    } else {
        __half2 h0 = __floats2half2_rn(a0, a1);
        __half2 h1 = __floats2half2_rn(a2, a3);
        __half2 h2 = __floats2half2_rn(a4, a5);
        __half2 h3 = __floats2half2_rn(a6, a7);
        uint4 o;
        o.x = *reinterpret_cast<uint32_t*>(&h0);
        o.y = *reinterpret_cast<uint32_t*>(&h1);
        o.z = *reinterpret_cast<uint32_t*>(&h2);
        o.w = *reinterpret_cast<uint32_t*>(&h3);
        reinterpret_cast<uint4*>(outv)[(size_t)row * 16 + hl] = o;
    }
}

// ---------------- kernel 2: spmm0 (feat x W) || adj scatter ----------------
// Blocks [0, SPMM_BLOCKS) run spmm layer 1; blocks [SPMM_BLOCKS, +SCAT_A_BLOCKS)
// scatter the adjacency. Independent work, concurrent inside one launch.
__global__ void __launch_bounds__(NT) fused_spmm0_scatter_adj(
        const int* __restrict__ adj_rows,
        const int* __restrict__ adj_cols,
        const float* __restrict__ adj_vals,
        const __half* __restrict__ w16,
        void* __restrict__ out_ha,
        const float* __restrict__ bias) {
    if (blockIdx.x < SPMM_BLOCKS) {
        spmm_body<0, CAP_F>(blockIdx.x, g_feat_cnt, g_feat_cv, w16, out_ha, bias);
    } else {
        int i = (blockIdx.x - SPMM_BLOCKS) * blockDim.x + threadIdx.x;
        if (i < NNZ_ADJ) {
            int r = __ldg(adj_rows + i);
            int p = atomicAdd(&g_adj_cnt[r], 1);
            if (p < CAP_A) {
                int2 cv;
                cv.x = __ldg(adj_cols + i) * 16;
                cv.y = __float_as_int(__ldg(adj_vals + i));
                g_adj_cv[(size_t)r * CAP_A + p] = cv;
            }
        }
    }
}

// ---------------- kernel 3: spmm1 (adj) || zero feat cnt -------------------
__global__ void __launch_bounds__(NT) fused_spmm1_zero_feat(
        const __half* __restrict__ in_ha,
        void* __restrict__ out_hb) {
    if (blockIdx.x < SPMM_BLOCKS) {
        spmm_body<1, CAP_A>(blockIdx.x, g_adj_cnt, g_adj_cv, in_ha, out_hb, nullptr);
    } else {
        int i = (blockIdx.x - SPMM_BLOCKS) * blockDim.x + threadIdx.x;
        if (i < N_NODES) g_feat_cnt[i] = 0;
    }
}

// ---------------- kernels 4/5: plain adj spmm ------------------------------
template <int MODE>
__global__ void __launch_bounds__(NT) spmm_adj_kernel(
        const __half* __restrict__ in_h,
        void* __restrict__ outv) {
    spmm_body<MODE, CAP_A>(blockIdx.x, g_adj_cnt, g_adj_cv, in_h, outv, nullptr);
}

// ---------------- tail: re-zero adj cursors for the next call --------------
__global__ void tail_zero_adj_kernel() {
    int i = blockIdx.x * blockDim.x + threadIdx.x;
    if (i < N_NODES) g_adj_cnt[i] = 0;
}

// ---------------- launch ---------------------------------------------------
extern "C" void kernel_launch(void* const* d_in, const int* in_sizes, int n_in,
                              void* d_out, int out_size) {
    const int*   feat_rows = (const int*)  d_in[0];
    const int*   feat_cols = (const int*)  d_in[1];
    const float* feat_vals = (const float*)d_in[2];
    const int*   adj_rows  = (const int*)  d_in[3];
    const int*   adj_cols  = (const int*)  d_in[4];
    const float* adj_vals  = (const float*)d_in[5];
    const float* weight    = (const float*)d_in[6];
    const float* bias      = (const float*)d_in[7];
    float*       out       = (float*)d_out;

    static __half* h_ha = nullptr;
    static __half* h_hb;
    static __half* h_w16;
    if (!h_ha) {
        cudaGetSymbolAddress((void**)&h_ha,  g_ha);
        cudaGetSymbolAddress((void**)&h_hb,  g_hb);
        cudaGetSymbolAddress((void**)&h_w16, g_w16);
    }

    // 1) feat scatter + W convert (cursors zero at entry — see invariant)
    scatter_feat_convert_kernel<<<SCAT_F_BLOCKS, NT>>>(feat_rows, feat_cols,
                                                       feat_vals, weight);
    // 2) spmm0 (feat x W + bias + relu -> ha) || adj scatter
    fused_spmm0_scatter_adj<<<SPMM_BLOCKS + SCAT_A_BLOCKS, NT>>>(
        adj_rows, adj_cols, adj_vals, h_w16, h_ha, bias);
    // 3) spmm1 (ha -> hb) || zero feat cnt
    fused_spmm1_zero_feat<<<SPMM_BLOCKS + ZERO_BLOCKS, NT>>>(h_ha, h_hb);
    // 4) spmm2 (hb -> ha)
    spmm_adj_kernel<1><<<SPMM_BLOCKS, NT>>>(h_hb, h_ha);
    // 5) spmm3 (ha -> out, fp32)
    spmm_adj_kernel<2><<<SPMM_BLOCKS, NT>>>(h_ha, out);
    // 6) zero adj cnt for next call
    tail_zero_adj_kernel<<<ZERO_BLOCKS, NT>>>();
}

// round 10
// speedup vs baseline: 1.0260x; 1.0260x over previous
#include <cuda_runtime.h>
#include <cuda_fp16.h>
#include <cstdint>

#define N_NODES   100000
#define IN_CH     2048
#define OUT_CH    128
#define NNZ_FEAT  2000000
#define NNZ_ADJ   1600000
#define CAP_F     128     // max feat row degree (Poisson(20))
#define CAP_A     96      // max adj  row degree (Poisson(16))

#define NT        256
#define SPMM_BLOCKS   (N_NODES / 16)                      // 6250 (exact; 8 warps x 2 rows)
#define SCAT_BLOCKS   ((NNZ_FEAT + NT - 1) / NT)          // 7813
#define ZERO_BLOCKS   ((N_NODES  + NT - 1) / NT)          // 391

// ---------------- static device scratch (no allocations allowed) ----------
// Invariant: g_feat_cnt / g_adj_cnt are ZERO at entry of every call (static
// init on first call; tail_zero_kernel restores at the end of every call).
__device__ int    g_feat_cnt[N_NODES];
__device__ int    g_adj_cnt [N_NODES];
__device__ int2   g_feat_cv [(size_t)N_NODES * CAP_F];   // .x = col*16, .y = bits(val)
__device__ int2   g_adj_cv  [(size_t)N_NODES * CAP_A];
__device__ __half g_w16     [IN_CH * OUT_CH];
__device__ __half g_ha      [(size_t)N_NODES * OUT_CH];  // ping
__device__ __half g_hb      [(size_t)N_NODES * OUT_CH];  // pong

// ---------------- packed f32x2 FMA (Blackwell FFMA2, PTX-only) -------------
__device__ __forceinline__ unsigned long long pack_dup(float v) {
    unsigned long long r;
    asm("mov.b64 %0, {%1, %1};" : "=l"(r) : "f"(v));
    return r;
}
__device__ __forceinline__ void ffma2(float& x, float& y, float hx, float hy,
                                      unsigned long long vv) {
    asm("{\n\t"
        ".reg .b64 ta, tb;\n\t"
        "mov.b64 ta, {%0, %1};\n\t"
        "mov.b64 tb, {%2, %3};\n\t"
        "fma.rn.f32x2 ta, tb, %4, ta;\n\t"
        "mov.b64 {%0, %1}, ta;\n\t"
        "}"
        : "+f"(x), "+f"(y) : "f"(hx), "f"(hy), "l"(vv));
}

// ---------------- scatter into buckets (+ fused weight convert) ------------
__global__ void scatter_convert_kernel(const int* __restrict__ feat_rows,
                                       const int* __restrict__ feat_cols,
                                       const float* __restrict__ feat_vals,
                                       const int* __restrict__ adj_rows,
                                       const int* __restrict__ adj_cols,
                                       const float* __restrict__ adj_vals,
                                       const float* __restrict__ w) {
    int i = blockIdx.x * blockDim.x + threadIdx.x;
    if (i < NNZ_FEAT) {
        int r = __ldg(feat_rows + i);
        int p = atomicAdd(&g_feat_cnt[r], 1);
        if (p < CAP_F) {
            int2 cv;
            cv.x = __ldg(feat_cols + i) * 16;
            cv.y = __float_as_int(__ldg(feat_vals + i));
            g_feat_cv[(size_t)r * CAP_F + p] = cv;
        }
    }
    if (i < NNZ_ADJ) {
        int r = __ldg(adj_rows + i);
        int p = atomicAdd(&g_adj_cnt[r], 1);
        if (p < CAP_A) {
            int2 cv;
            cv.x = __ldg(adj_cols + i) * 16;
            cv.y = __float_as_int(__ldg(adj_vals + i));
            g_adj_cv[(size_t)r * CAP_A + p] = cv;
        }
    }
    if (i < IN_CH * OUT_CH / 4) {
        float4 f = __ldg(reinterpret_cast<const float4*>(w) + i);
        __half2* o = reinterpret_cast<__half2*>(g_w16 + i * 4);
        o[0] = __floats2half2_rn(f.x, f.y);
        o[1] = __floats2half2_rn(f.z, f.w);
    }
}

// ---------------- SPMM: half-warp per row, 2-deep unroll -------------------
// Warp handles rows 2w, 2w+1. Lane covers 8 channels (uint4 = 16B). 2 LDG.128
// in flight; __launch_bounds__(256,6) caps regs (~42) for 75% occupancy.
// MODE 0: bias+relu, half out.  MODE 1: half out.  MODE 2: float out.
template <int MODE, int CAP>
__global__ void __launch_bounds__(NT, 6) spmm_kernel(
        const int* __restrict__ cnt,
        const int2* __restrict__ cv,
        const __half* __restrict__ dense16,
        void* __restrict__ outv,
        const float* __restrict__ bias) {
    int gw   = (blockIdx.x * blockDim.x + threadIdx.x) >> 5;
    int lane = threadIdx.x & 31;
    int hf   = lane >> 4;
    int hl   = lane & 15;
    int row  = gw * 2 + hf;
    if (row >= N_NODES) return;     // N even -> whole warp exits together

    int deg = __ldg(cnt + row);
    if (deg > CAP) deg = CAP;
    int degw = max(deg, __shfl_xor_sync(0xffffffffu, deg, 16));

    const int2* rowcv = cv + (size_t)row * CAP;
    const uint4* dp = reinterpret_cast<const uint4*>(dense16);  // 16 uint4 per row

    float a0=0.f,a1=0.f,a2=0.f,a3=0.f,a4=0.f,a5=0.f,a6=0.f,a7=0.f;

    for (int base = 0; base < degw; base += 16) {
        int2 p = make_int2(0, 0);                 // pad: c16=0, v=0 (harmless)
        if (base + hl < deg) p = __ldg(rowcv + base + hl);
        int n = degw - base;
        if (n > 16) n = 16;
        int nq = (n + 1) & ~1;
        for (int k = 0; k < nq; k += 2) {
            int c0 = __shfl_sync(0xffffffffu, p.x, k,     16);
            int c1 = __shfl_sync(0xffffffffu, p.x, k + 1, 16);
            unsigned long long v0 = pack_dup(__int_as_float(__shfl_sync(0xffffffffu, p.y, k,     16)));
            unsigned long long v1 = pack_dup(__int_as_float(__shfl_sync(0xffffffffu, p.y, k + 1, 16)));
            // 2 independent 16B gathers in flight (each serves one nnz per half)
            uint4 h0 = __ldg(dp + c0 + hl);
            uint4 h1 = __ldg(dp + c1 + hl);

            float2 f;
            f = __half22float2(*reinterpret_cast<__half2*>(&h0.x)); ffma2(a0,a1,f.x,f.y,v0);
            f = __half22float2(*reinterpret_cast<__half2*>(&h0.y)); ffma2(a2,a3,f.x,f.y,v0);
            f = __half22float2(*reinterpret_cast<__half2*>(&h0.z)); ffma2(a4,a5,f.x,f.y,v0);
            f = __half22float2(*reinterpret_cast<__half2*>(&h0.w)); ffma2(a6,a7,f.x,f.y,v0);

            f = __half22float2(*reinterpret_cast<__half2*>(&h1.x)); ffma2(a0,a1,f.x,f.y,v1);
            f = __half22float2(*reinterpret_cast<__half2*>(&h1.y)); ffma2(a2,a3,f.x,f.y,v1);
            f = __half22float2(*reinterpret_cast<__half2*>(&h1.z)); ffma2(a4,a5,f.x,f.y,v1);
            f = __half22float2(*reinterpret_cast<__half2*>(&h1.w)); ffma2(a6,a7,f.x,f.y,v1);
        }
    }

    if (MODE == 0) {
        const float4* b4 = reinterpret_cast<const float4*>(bias);
        float4 b0 = __ldg(b4 + hl * 2);
        float4 b1 = __ldg(b4 + hl * 2 + 1);
        a0 = fmaxf(a0 + b0.x, 0.f); a1 = fmaxf(a1 + b0.y, 0.f);
        a2 = fmaxf(a2 + b0.z, 0.f); a3 = fmaxf(a3 + b0.w, 0.f);
        a4 = fmaxf(a4 + b1.x, 0.f); a5 = fmaxf(a5 + b1.y, 0.f);
        a6 = fmaxf(a6 + b1.z, 0.f); a7 = fmaxf(a7 + b1.w, 0.f);
    }

    if (MODE == 2) {
        float4* o4 = reinterpret_cast<float4*>(outv);
        float4 o;
        o.x = a0; o.y = a1; o.z = a2; o.w = a3;
        o4[(size_t)row * 32 + hl * 2]     = o;
        o.x = a4; o.y = a5; o.z = a6; o.w = a7;
        o4[(size_t)row * 32 + hl * 2 + 1] = o;
    } else {
        __half2 h0 = __floats2half2_rn(a0, a1);
        __half2 h1 = __floats2half2_rn(a2, a3);
        __half2 h2 = __floats2half2_rn(a4, a5);
        __half2 h3 = __floats2half2_rn(a6, a7);
        uint4 o;
        o.x = *reinterpret_cast<uint32_t*>(&h0);
        o.y = *reinterpret_cast<uint32_t*>(&h1);
        o.z = *reinterpret_cast<uint32_t*>(&h2);
        o.w = *reinterpret_cast<uint32_t*>(&h3);
        reinterpret_cast<uint4*>(outv)[(size_t)row * 16 + hl] = o;
    }
}

// ---------------- tail: re-zero cursors for the next call ------------------
__global__ void tail_zero_kernel() {
    int i = blockIdx.x * blockDim.x + threadIdx.x;
    if (i < N_NODES) { g_feat_cnt[i] = 0; g_adj_cnt[i] = 0; }
}

// ---------------- launch ---------------------------------------------------
extern "C" void kernel_launch(void* const* d_in, const int* in_sizes, int n_in,
                              void* d_out, int out_size) {
    const int*   feat_rows = (const int*)  d_in[0];
    const int*   feat_cols = (const int*)  d_in[1];
    const float* feat_vals = (const float*)d_in[2];
    const int*   adj_rows  = (const int*)  d_in[3];
    const int*   adj_cols  = (const int*)  d_in[4];
    const float* adj_vals  = (const float*)d_in[5];
    const float* weight    = (const float*)d_in[6];
    const float* bias      = (const float*)d_in[7];
    float*       out       = (float*)d_out;

    static __half* h_ha = nullptr;
    static __half* h_hb;
    static __half* h_w16;
    static int *h_fcnt, *h_acnt;
    static int2 *h_fcv, *h_acv;
    if (!h_ha) {
        cudaGetSymbolAddress((void**)&h_ha,   g_ha);
        cudaGetSymbolAddress((void**)&h_hb,   g_hb);
        cudaGetSymbolAddress((void**)&h_w16,  g_w16);
        cudaGetSymbolAddress((void**)&h_fcnt, g_feat_cnt);
        cudaGetSymbolAddress((void**)&h_fcv,  g_feat_cv);
        cudaGetSymbolAddress((void**)&h_acnt, g_adj_cnt);
        cudaGetSymbolAddress((void**)&h_acv,  g_adj_cv);
    }

    // 1) scatter both matrices into buckets + convert W (cursors zero at entry)
    scatter_convert_kernel<<<SCAT_BLOCKS, NT>>>(
        feat_rows, feat_cols, feat_vals, adj_rows, adj_cols, adj_vals, weight);

    // 2) SPMM chain
    spmm_kernel<0, CAP_F><<<SPMM_BLOCKS, NT>>>(h_fcnt, h_fcv, h_w16, h_ha, bias);
    spmm_kernel<1, CAP_A><<<SPMM_BLOCKS, NT>>>(h_acnt, h_acv, h_ha, h_hb, nullptr);
    spmm_kernel<1, CAP_A><<<SPMM_BLOCKS, NT>>>(h_acnt, h_acv, h_hb, h_ha, nullptr);
    spmm_kernel<2, CAP_A><<<SPMM_BLOCKS, NT>>>(h_acnt, h_acv, h_ha, out, nullptr);

    // 3) restore zero-cursor invariant
    tail_zero_kernel<<<ZERO_BLOCKS, NT>>>();
}